// round 9
// baseline (speedup 1.0000x reference)
#include <cuda_runtime.h>
#include <cuda_fp16.h>

#define NN 100000
#define NE 1600000
#define NPART 98   // ceil(NN/1024)

// ---------------- scratch (static device globals; no allocs) ----------------
__device__ int    g_cnt[NN];
__device__ int    g_off[NN + 1];
__device__ int    g_pos[NN];
__device__ int    g_part[NPART];
__device__ int    g_srcs[NE];
__device__ float  g_B0[256 * 128];             // rows 0..127 = W_l0, rows 128..255 = W_r0
__device__ float  g_B1[128 * 128];             // [W_l1 | W_r1], K=128 x 128
__device__ __half g_x16[(size_t)NN * 128];     // fp16 copy of x (gather operand)
__device__ float  g_m0[(size_t)NN * 128];      // mean-aggregated x
__device__ float  g_h[(size_t)NN * 128];       // relu'd layer-0 output
__device__ __half g_y16[(size_t)NN * 64];      // y1 = h @ W_l1 (fp16 gather operand)
__device__ float  g_z1[(size_t)NN * 64];       // z1 = h @ W_r1 (fp32 root term)

// ---------------- tf32 mma helpers ----------------
__device__ __forceinline__ unsigned f2tf32(float f) {
    unsigned r;
    asm("cvt.rna.tf32.f32 %0, %1;" : "=r"(r) : "f"(f));
    return r;
}
__device__ __forceinline__ unsigned sptr(const void* p) {
    return (unsigned)__cvta_generic_to_shared(p);
}
#define LDSM4(R, addr)                                                              \
    asm volatile("ldmatrix.sync.aligned.m8n8.x4.shared.b16 {%0,%1,%2,%3}, [%4];"    \
                 : "=r"((R)[0]), "=r"((R)[1]), "=r"((R)[2]), "=r"((R)[3])           \
                 : "r"(addr))
__device__ __forceinline__ void mma_tf32(float* c, const unsigned* a, unsigned b0, unsigned b1) {
    asm volatile(
        "mma.sync.aligned.m16n8k8.row.col.f32.tf32.tf32.f32 "
        "{%0,%1,%2,%3},{%4,%5,%6,%7},{%8,%9},{%0,%1,%2,%3};"
        : "+f"(c[0]), "+f"(c[1]), "+f"(c[2]), "+f"(c[3])
        : "r"(a[0]), "r"(a[1]), "r"(a[2]), "r"(a[3]), "r"(b0), "r"(b1));
}

// ---------------- CSR build ----------------
__global__ void k_zero() {
    int i = blockIdx.x * blockDim.x + threadIdx.x;
    if (i < NN) g_cnt[i] = 0;
}

// edge_index is int32 (JAX x64 disabled).
__global__ void k_count(const int* __restrict__ ei) {
    int e = blockIdx.x * blockDim.x + threadIdx.x;
    if (e < NE) {
        unsigned d = (unsigned)ei[NE + e];
        if (d < NN) atomicAdd(&g_cnt[d], 1);
    }
}

__global__ void k_scanA() {  // grid NPART, block 1024: block sums
    int i = blockIdx.x * 1024 + threadIdx.x;
    int v = (i < NN) ? g_cnt[i] : 0;
    __shared__ int ws[32];
    int lane = threadIdx.x & 31, w = threadIdx.x >> 5;
#pragma unroll
    for (int d = 16; d; d >>= 1) v += __shfl_down_sync(~0u, v, d);
    if (!lane) ws[w] = v;
    __syncthreads();
    if (!w) {
        int s = ws[lane];
#pragma unroll
        for (int d = 16; d; d >>= 1) s += __shfl_down_sync(~0u, s, d);
        if (!lane) g_part[blockIdx.x] = s;
    }
}

__global__ void k_scanB() {  // 1 block: exclusive scan of partials
    if (threadIdx.x == 0) {
        int run = 0;
        for (int b = 0; b < NPART; b++) {
            int c = g_part[b];
            g_part[b] = run;
            run += c;
        }
        g_off[NN] = run;
    }
}

__global__ void k_scanC() {  // grid NPART, block 1024: local exclusive scan + offset
    int i = blockIdx.x * 1024 + threadIdx.x;
    int c = (i < NN) ? g_cnt[i] : 0;
    int v = c;
    int lane = threadIdx.x & 31, w = threadIdx.x >> 5;
#pragma unroll
    for (int d = 1; d < 32; d <<= 1) {
        int t = __shfl_up_sync(~0u, v, d);
        if (lane >= d) v += t;
    }
    __shared__ int ws[32];
    if (lane == 31) ws[w] = v;
    __syncthreads();
    if (!w) {
        int s = ws[lane];
#pragma unroll
        for (int d = 1; d < 32; d <<= 1) {
            int t = __shfl_up_sync(~0u, s, d);
            if (lane >= d) s += t;
        }
        ws[lane] = s;
    }
    __syncthreads();
    int excl = v - c + (w ? ws[w - 1] : 0) + g_part[blockIdx.x];
    if (i < NN) {
        g_off[i] = excl;
        g_pos[i] = excl;
    }
}

__global__ void k_scatter(const int* __restrict__ ei) {
    int e = blockIdx.x * blockDim.x + threadIdx.x;
    if (e < NE) {
        unsigned d = (unsigned)ei[NE + e];
        if (d < NN) {
            int p = atomicAdd(&g_pos[d], 1);
            unsigned s = (unsigned)ei[e];
            g_srcs[p] = (s < NN) ? (int)s : 0;
        }
    }
}

// ---------------- pack weights + fp16 copy of x ----------------
__global__ void k_pack(const float* __restrict__ Wl0, const float* __restrict__ Wr0,
                       const float* __restrict__ Wl1, const float* __restrict__ Wr1) {
    int i = blockIdx.x * blockDim.x + threadIdx.x;
    if (i < 256 * 128) {
        int k = i >> 7, j = i & 127;
        g_B0[i] = (k < 128) ? Wl0[k * 128 + j] : Wr0[(k - 128) * 128 + j];
    }
    if (i < 128 * 128) {
        int k = i >> 7, j = i & 127;
        g_B1[i] = (j < 64) ? Wl1[(k << 6) + j] : Wr1[(k << 6) + (j - 64)];
    }
}

__global__ void k_x16(const float* __restrict__ x) {
    size_t i = (size_t)(blockIdx.x * blockDim.x + threadIdx.x) * 4;
    if (i < (size_t)NN * 128) {
        float4 v = *(const float4*)&x[i];
        __half2 h0 = __floats2half2_rn(v.x, v.y);
        __half2 h1 = __floats2half2_rn(v.z, v.w);
        *(__half2*)&g_x16[i] = h0;
        *(__half2*)&g_x16[i + 2] = h1;
    }
}

// ---------------- input-space mean aggregation: m0 = mean(x16[src]) ----------------
// warp per node; lane handles 4 cols (8B fp16); 2-deep unrolled gather.
__global__ void k_aggx() {
    int node = blockIdx.x * 8 + (threadIdx.x >> 5);
    int lane = threadIdx.x & 31;
    if (node >= NN) return;
    int beg = g_off[node], end = g_off[node + 1];
    float inv = 1.0f / (float)max(end - beg, 1);
    float4 a0 = make_float4(0.f, 0.f, 0.f, 0.f);
    float4 a1 = make_float4(0.f, 0.f, 0.f, 0.f);
    int e = beg;
    for (; e + 2 <= end; e += 2) {
        int s0 = g_srcs[e], s1 = g_srcs[e + 1];
        uint2 u0 = *(const uint2*)&g_x16[(size_t)s0 * 128 + lane * 4];
        uint2 u1 = *(const uint2*)&g_x16[(size_t)s1 * 128 + lane * 4];
        float2 p0 = __half22float2(*(__half2*)&u0.x);
        float2 p1 = __half22float2(*(__half2*)&u0.y);
        float2 q0 = __half22float2(*(__half2*)&u1.x);
        float2 q1 = __half22float2(*(__half2*)&u1.y);
        a0.x += p0.x; a0.y += p0.y; a0.z += p1.x; a0.w += p1.y;
        a1.x += q0.x; a1.y += q0.y; a1.z += q1.x; a1.w += q1.y;
    }
    if (e < end) {
        int s0 = g_srcs[e];
        uint2 u0 = *(const uint2*)&g_x16[(size_t)s0 * 128 + lane * 4];
        float2 p0 = __half22float2(*(__half2*)&u0.x);
        float2 p1 = __half22float2(*(__half2*)&u0.y);
        a0.x += p0.x; a0.y += p0.y; a0.z += p1.x; a0.w += p1.y;
    }
    float4 r;
    r.x = (a0.x + a1.x) * inv;
    r.y = (a0.y + a1.y) * inv;
    r.z = (a0.z + a1.z) * inv;
    r.w = (a0.w + a1.w) * inv;
    *(float4*)&g_m0[(size_t)node * 128 + lane * 4] = r;
}

// ---------------- tf32 tensor-core GEMM ----------------
// PHASE 0: C = concat(m0, x) @ B0  (K=256), epilogue bias+relu -> g_h
// PHASE 1: C = g_h @ B1 (K=128); warp_n==0 cols->y16 (fp16), warp_n==64 cols->z1 (fp32)
// BM=128, BN=128, BK=16; 256 threads = 8 warps (4m x 2n), warp tile 32x64.
template <int PHASE>
__global__ __launch_bounds__(256, 2) void k_gemm(const float* __restrict__ x,
                                                 const float* __restrict__ bias) {
    const int K = (PHASE == 0) ? 256 : 128;
    const float* __restrict__ Bsrc = (PHASE == 0) ? g_B0 : g_B1;

    __shared__ unsigned As[128][20];
    __shared__ unsigned Bs[128][20];

    int tid = threadIdx.x;
    int lane = tid & 31;
    int wid = tid >> 5;
    int warp_m = (wid >> 1) * 32;
    int warp_n = (wid & 1) * 64;
    int m0b = blockIdx.x * 128;

    int aRow = tid >> 1;
    int kLo = (tid & 1) * 8;

    float acc[2][8][4];
#pragma unroll
    for (int mi = 0; mi < 2; mi++)
#pragma unroll
        for (int ni = 0; ni < 8; ni++)
#pragma unroll
            for (int q = 0; q < 4; q++) acc[mi][ni][q] = 0.f;

    int g = lane >> 3, r = lane & 7;

    for (int k0 = 0; k0 < K; k0 += 16) {
        const float* __restrict__ A = (PHASE == 0) ? ((k0 < 128) ? g_m0 : x) : g_h;
        int kk = (k0 & 127) + kLo;
        int grow = m0b + aRow;
#pragma unroll
        for (int q = 0; q < 2; q++) {
            float4 av = make_float4(0.f, 0.f, 0.f, 0.f);
            if (grow < NN) av = *(const float4*)&A[(size_t)grow * 128 + kk + q * 4];
            unsigned u0 = f2tf32(av.x), u1 = f2tf32(av.y), u2 = f2tf32(av.z), u3 = f2tf32(av.w);
            *(uint4*)&As[aRow][kLo + q * 4] = make_uint4(u0, u1, u2, u3);
        }
        {
            int bN = tid >> 1;
            int kq = (tid & 1) * 8;
#pragma unroll
            for (int j = 0; j < 8; j++)
                Bs[bN][kq + j] = f2tf32(Bsrc[(size_t)(k0 + kq + j) * 128 + bN]);
        }
        __syncthreads();

#pragma unroll
        for (int ks = 0; ks < 16; ks += 8) {
            unsigned aF[2][4], bF[4][4];
#pragma unroll
            for (int mi = 0; mi < 2; mi++) {
                int row = warp_m + mi * 16 + (g & 1) * 8 + r;
                int col = ks + (g >> 1) * 4;
                LDSM4(aF[mi], sptr(&As[row][col]));
            }
#pragma unroll
            for (int nt = 0; nt < 4; nt++) {
                int row = warp_n + nt * 16 + (g >> 1) * 8 + r;
                int col = ks + (g & 1) * 4;
                LDSM4(bF[nt], sptr(&Bs[row][col]));
            }
#pragma unroll
            for (int mi = 0; mi < 2; mi++)
#pragma unroll
                for (int nt = 0; nt < 4; nt++) {
                    mma_tf32(acc[mi][nt * 2 + 0], aF[mi], bF[nt][0], bF[nt][1]);
                    mma_tf32(acc[mi][nt * 2 + 1], aF[mi], bF[nt][2], bF[nt][3]);
                }
        }
        __syncthreads();
    }

    int rrow = lane >> 2;
    int cquad = (lane & 3) * 2;
#pragma unroll
    for (int mi = 0; mi < 2; mi++) {
        int r0 = m0b + warp_m + mi * 16 + rrow;
#pragma unroll
        for (int ni = 0; ni < 8; ni++) {
            int col = warp_n + ni * 8 + cquad;
            float* c = acc[mi][ni];
            if (PHASE == 0) {
                float b0v = bias[col], b1v = bias[col + 1];
                if (r0 < NN) {
                    float2 v = make_float2(fmaxf(c[0] + b0v, 0.f), fmaxf(c[1] + b1v, 0.f));
                    *(float2*)&g_h[(size_t)r0 * 128 + col] = v;
                }
                if (r0 + 8 < NN) {
                    float2 v = make_float2(fmaxf(c[2] + b0v, 0.f), fmaxf(c[3] + b1v, 0.f));
                    *(float2*)&g_h[(size_t)(r0 + 8) * 128 + col] = v;
                }
            } else if (warp_n == 0) {  // y1 columns -> fp16 gather operand
                if (r0 < NN)
                    *(__half2*)&g_y16[(size_t)r0 * 64 + col] = __floats2half2_rn(c[0], c[1]);
                if (r0 + 8 < NN)
                    *(__half2*)&g_y16[(size_t)(r0 + 8) * 64 + col] = __floats2half2_rn(c[2], c[3]);
            } else {  // z1 columns (root term) -> fp32 exact
                int zc = col - 64;
                if (r0 < NN)
                    *(float2*)&g_z1[(size_t)r0 * 64 + zc] = make_float2(c[0], c[1]);
                if (r0 + 8 < NN)
                    *(float2*)&g_z1[(size_t)(r0 + 8) * 64 + zc] = make_float2(c[2], c[3]);
            }
        }
    }
}

// ---------------- layer-1 aggregate + bias + root ----------------
// warp per node; lane handles 2 cols (4B fp16); 2-deep unrolled gather.
__global__ void k_agg2(const float* __restrict__ bias, float* __restrict__ out) {
    int node = blockIdx.x * 8 + (threadIdx.x >> 5);
    int lane = threadIdx.x & 31;
    if (node >= NN) return;
    int beg = g_off[node], end = g_off[node + 1];
    float inv = 1.0f / (float)max(end - beg, 1);
    float2 a0 = make_float2(0.f, 0.f), a1 = make_float2(0.f, 0.f);
    int e = beg;
    for (; e + 2 <= end; e += 2) {
        int s0 = g_srcs[e], s1 = g_srcs[e + 1];
        float2 v0 = __half22float2(*(const __half2*)&g_y16[(size_t)s0 * 64 + lane * 2]);
        float2 v1 = __half22float2(*(const __half2*)&g_y16[(size_t)s1 * 64 + lane * 2]);
        a0.x += v0.x; a0.y += v0.y;
        a1.x += v1.x; a1.y += v1.y;
    }
    if (e < end) {
        int s0 = g_srcs[e];
        float2 v0 = __half22float2(*(const __half2*)&g_y16[(size_t)s0 * 64 + lane * 2]);
        a0.x += v0.x; a0.y += v0.y;
    }
    float2 z = *(const float2*)&g_z1[(size_t)node * 64 + lane * 2];
    float2 b = *(const float2*)&bias[lane * 2];
    float2 r;
    r.x = fmaf(a0.x + a1.x, inv, b.x + z.x);
    r.y = fmaf(a0.y + a1.y, inv, b.y + z.y);
    *(float2*)&out[(size_t)node * 64 + lane * 2] = r;
}

// ---------------- launch ----------------
extern "C" void kernel_launch(void* const* d_in, const int* in_sizes, int n_in,
                              void* d_out, int out_size) {
    const float* x = (const float*)d_in[0];
    const int* ei = (const int*)d_in[1];          // int32 edge_index [2, NE]
    const float* Wl0 = (const float*)d_in[2];
    const float* bl0 = (const float*)d_in[3];
    const float* Wr0 = (const float*)d_in[4];
    const float* Wl1 = (const float*)d_in[5];
    const float* bl1 = (const float*)d_in[6];
    const float* Wr1 = (const float*)d_in[7];
    float* out = (float*)d_out;

    // CSR build (every launch; graph-replay safe)
    k_zero<<<(NN + 255) / 256, 256>>>();
    k_count<<<(NE + 255) / 256, 256>>>(ei);
    k_scanA<<<NPART, 1024>>>();
    k_scanB<<<1, 32>>>();
    k_scanC<<<NPART, 1024>>>();
    k_scatter<<<(NE + 255) / 256, 256>>>(ei);
    k_pack<<<(256 * 128 + 255) / 256, 256>>>(Wl0, Wr0, Wl1, Wr1);
    k_x16<<<((NN * 128 / 4) + 255) / 256, 256>>>(x);

    int mt = (NN + 127) / 128;  // 782
    // m0 = mean(x16[src])  (fp16 gather, halved L2 traffic)
    k_aggx<<<(NN + 7) / 8, 256>>>();
    // h = relu(m0 @ Wl0 + x @ Wr0 + b0)   (tf32 tensor cores)
    k_gemm<0><<<mt, 256>>>(x, bl0);
    // y16 = h @ W_l1 (fp16), z1 = h @ W_r1 (fp32)
    k_gemm<1><<<mt, 256>>>(nullptr, nullptr);
    // out = mean_agg(y16) + b1 + z1
    k_agg2<<<(NN + 7) / 8, 256>>>(bl1, out);
}